// round 11
// baseline (speedup 1.0000x reference)
#include <cuda_runtime.h>

// BeliefMatchingLoss: pred [8,19,512,512] f32, target [8,512,512] int32 -> scalar f32
// Single-kernel last-block reduction; self-resetting for graph replay.
//
// loss_pix = 0.01*kl + psi(a0) - psi(a_ans)
// kl = lnG(a0) - (a0-19)*psi(a0) + sum_c g(a_c),  a_c = exp(p_c), a0 = sum a_c
// Per-class g via shift-1 (z=x+1, u=1/z, r=1/(x*z)):
//   g ~= p + 1/x + z - 1.5*ln z + (5/6)u + (1/6)u^2 + u^3/90 - (C+1.5)
// Identities: 1/x = u + r (folds into poly), sum ln z = LN2*lg2(prod w) - sum p.
//
// Layout: 4 px/thread as TWO independent f32x2 lanes (ILP x2), 128-thr blocks.
// Classes 0..17 staged via 16B cp.async.cg (one LDS.128 per class covers all
// 4 px), class 18 via one LDG.128.nc held in regs. Answer logits gathered
// from global (L2 hits). One commit group per quad; compute drafts behind.

typedef unsigned long long u64;

#define HW_   (512 * 512)
#define NC_   19
#define NSTG  18
#define NPIX_ (8 * HW_)
#define TPB_  128
#define NBLK_ (NPIX_ / (4 * TPB_))   // 4096

#define LN2F        0.6931471805599453f
#define LOG2EF      1.4426950408889634f
#define HALF_LN_2PI 0.91893853320467274f

__device__ double             g_sum    = 0.0;
__device__ unsigned long long g_cnt    = 0ull;
__device__ unsigned int       g_arrive = 0u;

// ---- packed f32x2 helpers (u64 = {lo,hi} fp32 pair) ----
__device__ __forceinline__ u64 pk2(float a, float b) {
    u64 r; asm("mov.b64 %0,{%1,%2};" : "=l"(r) : "f"(a), "f"(b)); return r;
}
__device__ __forceinline__ void upk2(u64 v, float& a, float& b) {
    asm("mov.b64 {%0,%1},%2;" : "=f"(a), "=f"(b) : "l"(v));
}
__device__ __forceinline__ u64 f2fma(u64 a, u64 b, u64 c) {
    u64 d; asm("fma.rn.f32x2 %0,%1,%2,%3;" : "=l"(d) : "l"(a), "l"(b), "l"(c)); return d;
}
__device__ __forceinline__ u64 f2mul(u64 a, u64 b) {
    u64 d; asm("mul.rn.f32x2 %0,%1,%2;" : "=l"(d) : "l"(a), "l"(b)); return d;
}
__device__ __forceinline__ u64 f2add(u64 a, u64 b) {
    u64 d; asm("add.rn.f32x2 %0,%1,%2;" : "=l"(d) : "l"(a), "l"(b)); return d;
}
__device__ __forceinline__ u64 f2sub(u64 a, u64 b) {
    return f2fma(b, pk2(-1.0f, -1.0f), a);
}
__device__ __forceinline__ float ex2f(float x) { float r; asm("ex2.approx.f32 %0,%1;" : "=f"(r) : "f"(x)); return r; }
__device__ __forceinline__ float lg2f_(float x){ float r; asm("lg2.approx.f32 %0,%1;" : "=f"(r) : "f"(x)); return r; }
__device__ __forceinline__ float rcpf_(float x){ float r; asm("rcp.approx.f32 %0,%1;" : "=f"(r) : "f"(x)); return r; }
__device__ __forceinline__ u64 rcp_2(u64 v) { float a, b; upk2(v, a, b); return pk2(rcpf_(a), rcpf_(b)); }
__device__ __forceinline__ u64 lg2_2(u64 v) { float a, b; upk2(v, a, b); return pk2(lg2f_(a), lg2f_(b)); }

// packed per-lane epilogue: psi+lnG at a0 (shift-2), psi at x_ans, combine
__device__ __forceinline__ u64 lane_loss(u64 a0v, u64 accP, u64 accR, u64 accU,
                                         u64 lgw, u64 xa) {
    const u64 K2p   = pk2(2.0f, 2.0f);
    const u64 K3p   = pk2(3.0f, 3.0f);
    const u64 KHp   = pk2(0.5f, 0.5f);
    const u64 K12p  = pk2(1.0f / 12.0f, 1.0f / 12.0f);
    const u64 Km120 = pk2(-1.0f / 120.0f, -1.0f / 120.0f);
    const u64 Km360 = pk2(-1.0f / 360.0f, -1.0f / 360.0f);
    const u64 KLN2  = pk2(LN2F, LN2F);

    // psi0/lg0 at a0
    u64 z0   = f2add(a0v, K2p);
    u64 P0   = f2fma(a0v, a0v, a0v);
    u64 r0   = rcp_2(f2mul(P0, z0));
    u64 S0   = f2mul(f2fma(K2p, P0, f2fma(K3p, a0v, K2p)), r0);
    u64 rz   = f2mul(P0, r0);
    u64 rz2  = f2mul(rz, rz);
    u64 lnz0 = f2mul(lg2_2(z0), KLN2);
    u64 lnP0 = f2mul(lg2_2(P0), KLN2);
    u64 cv   = f2fma(rz, KHp, f2mul(rz2, f2fma(rz2, Km120, K12p)));
    u64 tv_  = f2mul(rz, f2fma(rz2, Km360, K12p));
    u64 psi0 = f2sub(f2sub(lnz0, cv), S0);
    u64 lg0  = f2fma(f2sub(z0, KHp), lnz0, f2sub(tv_, z0));
    lg0 = f2add(f2sub(lg0, lnP0), pk2(HALF_LN_2PI, HALF_LN_2PI));

    // psia at x_ans
    u64 za   = f2add(xa, K2p);
    u64 Pa   = f2fma(xa, xa, xa);
    u64 ra   = rcp_2(f2mul(Pa, za));
    u64 Sa   = f2mul(f2fma(K2p, Pa, f2fma(K3p, xa, K2p)), ra);
    u64 rza  = f2mul(Pa, ra);
    u64 rza2 = f2mul(rza, rza);
    u64 ca   = f2fma(rza, KHp, f2mul(rza2, f2fma(rza2, Km120, K12p)));
    u64 psia = f2sub(f2sub(f2mul(lg2_2(za), KLN2), ca), Sa);

    // sum_g = 2.5*accP - 1.5*LN2*lgw + accR + accU + a0 + KADD
    const float KADDf = 19.0f * (1.0f - 1.5f - HALF_LN_2PI);
    u64 sumg = f2fma(pk2(2.5f, 2.5f), accP,
               f2fma(pk2(-1.5f * LN2F, -1.5f * LN2F), lgw, f2add(accR, accU)));
    sumg = f2add(sumg, f2add(a0v, pk2(KADDf, KADDf)));

    u64 kl = f2fma(f2sub(pk2(19.0f, 19.0f), a0v), psi0, f2add(lg0, sumg));
    return f2fma(pk2(0.01f, 0.01f), kl, f2sub(psi0, psia));
}

__global__ __launch_bounds__(TPB_, 6) void bml_main(const float* __restrict__ pred,
                                                    const int*  __restrict__ tgt,
                                                    float*      __restrict__ out) {
    __shared__ __align__(16) u64 smq[NSTG * TPB_ * 2];   // 36864 B: 16B/thread/class
    __shared__ float s_l[4];
    __shared__ int   s_v[4];

    unsigned tid = threadIdx.x;
    int tix = blockIdx.x * TPB_ + (int)tid;
    int pix = tix * 4;
    int b   = pix >> 18;
    int hw  = pix & (HW_ - 1);
    const float* pp = pred + (size_t)b * NC_ * HW_ + hw;

    unsigned sbase;
    asm("{ .reg .u64 t; cvta.to.shared.u64 t, %1; cvt.u32.u64 %0, t; }"
        : "=r"(sbase) : "l"(smq));
    unsigned stid = sbase + tid * 16u;

    // ---- stage classes 0..17: 16B cp.async.cg, one commit group per quad ----
#define CPA(c) asm volatile( \
        "cp.async.cg.shared.global [%0], [%1], 16;" \
        :: "r"(stid + (unsigned)((c) * 2048)), "l"(pp + (size_t)(c) * HW_) : "memory")
#define CG() asm volatile("cp.async.commit_group;" ::: "memory")
    CPA(0);  CPA(1);  CPA(2);  CPA(3);  CG();
    CPA(4);  CPA(5);  CPA(6);  CPA(7);  CG();
    CPA(8);  CPA(9);  CPA(10); CPA(11); CG();
    CPA(12); CPA(13); CPA(14); CPA(15); CG();
    CPA(16); CPA(17);                   CG();
#undef CPA
#undef CG

    // class 18 direct (held in regs; consumed in the tail group)
    u64 p18A, p18B;
    asm("ld.global.nc.v2.u64 {%0,%1},[%2];"
        : "=l"(p18A), "=l"(p18B) : "l"(pp + (size_t)18 * HW_));

    // targets + answer-class gathers (global; DRAM->L2 shared with cp.async)
    int4 tv = *reinterpret_cast<const int4*>(tgt + pix);
    bool ig0 = (tv.x == 255), ig1 = (tv.y == 255), ig2 = (tv.z == 255), ig3 = (tv.w == 255);
    int ta0 = ig0 ? 0 : tv.x;
    int ta1 = ig1 ? 0 : tv.y;
    int ta2 = ig2 ? 0 : tv.z;
    int ta3 = ig3 ? 0 : tv.w;
    float pa0 = __ldg(pp + (size_t)ta0 * HW_ + 0);
    float pa1 = __ldg(pp + (size_t)ta1 * HW_ + 1);
    float pa2 = __ldg(pp + (size_t)ta2 * HW_ + 2);
    float pa3 = __ldg(pp + (size_t)ta3 * HW_ + 3);

    const u64 KL2E = pk2(LOG2EF, LOG2EF);
    const u64 K1   = pk2(1.0f, 1.0f);
    const u64 Ca   = pk2(11.0f / 6.0f, 11.0f / 6.0f);   // 5/6 + 1 (1/x fold)
    const u64 Cb   = pk2(0.17333333f, 0.17333333f);     // 1/6 + 1/150 (u^3 fold)

    u64 accU[2] = {pk2(0.0f, 0.0f), pk2(0.0f, 0.0f)};
    u64 accR[2] = {accU[0], accU[0]};
    u64 accP[2] = {accU[0], accU[0]};
    u64 a0v [2] = {accU[0], accU[0]};
    u64 lgw [2] = {accU[0], accU[0]};

#define WAITG(n) asm volatile("cp.async.wait_group %0;" :: "n"(n) : "memory")

#define LDSQ(pvA, pvB, c) asm volatile("ld.shared.v2.b64 {%0,%1},[%2];" \
        : "=l"(pvA), "=l"(pvB) : "r"(stid + (unsigned)((c) * 2048)))

    // lane stage1: accumulate p, exp, form z and w=x*z
#define S1(pv, L, xx, ww) do {                                                \
        accP[L] = f2add(accP[L], pv);                                         \
        u64 e = f2mul(pv, KL2E);                                              \
        float el, eh; upk2(e, el, eh);                                        \
        (xx) = pk2(ex2f(el), ex2f(eh));                                       \
        u64 zz = f2add((xx), K1);                                             \
        (ww) = f2mul((xx), zz);                                               \
    } while (0)

#define S2(L, xx, rr) do {                                                    \
        u64 u_ = f2mul((xx), (rr));                                           \
        u64 q  = f2fma(u_, Cb, Ca);                                           \
        accU[L] = f2fma(u_, q, accU[L]);                                      \
        accR[L] = f2add(accR[L], (rr));                                       \
        a0v[L]  = f2add(a0v[L], (xx));                                        \
    } while (0)

#define GRP4(L, x0, x1, x2, x3, w0, w1, w2, w3) do {                          \
        u64 Wab = f2mul(w0, w1);                                              \
        u64 Wcd = f2mul(w2, w3);                                              \
        u64 Wq  = f2mul(Wab, Wcd);                                            \
        lgw[L] = f2add(lgw[L], lg2_2(Wq));                                    \
        u64 rr  = rcp_2(Wq);                                                  \
        u64 rab = f2mul(rr, Wcd);                                             \
        u64 rcd = f2mul(rr, Wab);                                             \
        S2(L, x0, f2mul(rab, w1));                                            \
        S2(L, x1, f2mul(rab, w0));                                            \
        S2(L, x2, f2mul(rcd, w3));                                            \
        S2(L, x3, f2mul(rcd, w2));                                            \
    } while (0)

#define QUAD(c0, wg) do {                                                     \
        WAITG(wg);                                                            \
        u64 xA0, xA1, xA2, xA3, wA0, wA1, wA2, wA3;                           \
        u64 xB0, xB1, xB2, xB3, wB0, wB1, wB2, wB3;                           \
        u64 pA, pB;                                                           \
        LDSQ(pA, pB, (c0) + 0); S1(pA, 0, xA0, wA0); S1(pB, 1, xB0, wB0);     \
        LDSQ(pA, pB, (c0) + 1); S1(pA, 0, xA1, wA1); S1(pB, 1, xB1, wB1);     \
        LDSQ(pA, pB, (c0) + 2); S1(pA, 0, xA2, wA2); S1(pB, 1, xB2, wB2);     \
        LDSQ(pA, pB, (c0) + 3); S1(pA, 0, xA3, wA3); S1(pB, 1, xB3, wB3);     \
        GRP4(0, xA0, xA1, xA2, xA3, wA0, wA1, wA2, wA3);                      \
        GRP4(1, xB0, xB1, xB2, xB3, wB0, wB1, wB2, wB3);                      \
    } while (0)

    QUAD(0, 4); QUAD(4, 3); QUAD(8, 2); QUAD(12, 1);
    { // tail group of 3: classes 16,17 from smem, 18 from regs
        WAITG(0);
        u64 xA0, xA1, xA2, wA0, wA1, wA2;
        u64 xB0, xB1, xB2, wB0, wB1, wB2;
        u64 pA, pB;
        LDSQ(pA, pB, 16); S1(pA, 0, xA0, wA0); S1(pB, 1, xB0, wB0);
        LDSQ(pA, pB, 17); S1(pA, 0, xA1, wA1); S1(pB, 1, xB1, wB1);
        S1(p18A, 0, xA2, wA2); S1(p18B, 1, xB2, wB2);
#define GRP3(L, x0, x1, x2, w0, w1, w2) do {                                  \
        u64 Wab = f2mul(w0, w1);                                              \
        u64 Wq  = f2mul(Wab, w2);                                             \
        lgw[L] = f2add(lgw[L], lg2_2(Wq));                                    \
        u64 rr  = rcp_2(Wq);                                                  \
        u64 rab = f2mul(rr, w2);                                              \
        S2(L, x0, f2mul(rab, w1));                                            \
        S2(L, x1, f2mul(rab, w0));                                            \
        S2(L, x2, f2mul(rr, Wab));                                            \
    } while (0)
        GRP3(0, xA0, xA1, xA2, wA0, wA1, wA2);
        GRP3(1, xB0, xB1, xB2, wB0, wB1, wB2);
#undef GRP3
    }
#undef QUAD
#undef GRP4
#undef S1
#undef S2
#undef LDSQ
#undef WAITG

    // per-lane packed epilogues
    u64 xaA = pk2(ex2f(pa0 * LOG2EF), ex2f(pa1 * LOG2EF));
    u64 xaB = pk2(ex2f(pa2 * LOG2EF), ex2f(pa3 * LOG2EF));
    u64 lA = lane_loss(a0v[0], accP[0], accR[0], accU[0], lgw[0], xaA);
    u64 lB = lane_loss(a0v[1], accP[1], accR[1], accU[1], lgw[1], xaB);

    float l0, l1, l2, l3;
    upk2(lA, l0, l1);
    upk2(lB, l2, l3);
    if (ig0) l0 = 0.0f;
    if (ig1) l1 = 0.0f;
    if (ig2) l2 = 0.0f;
    if (ig3) l3 = 0.0f;
    float loss = (l0 + l1) + (l2 + l3);

    unsigned m0 = __ballot_sync(0xffffffffu, ig0);
    unsigned m1 = __ballot_sync(0xffffffffu, ig1);
    unsigned m2 = __ballot_sync(0xffffffffu, ig2);
    unsigned m3 = __ballot_sync(0xffffffffu, ig3);
    int valid_w = 128 - __popc(m0) - __popc(m1) - __popc(m2) - __popc(m3);

#pragma unroll
    for (int o = 16; o; o >>= 1)
        loss += __shfl_down_sync(0xffffffffu, loss, o);

    int wid = threadIdx.x >> 5;
    int lid = threadIdx.x & 31;
    if (lid == 0) { s_l[wid] = loss; s_v[wid] = valid_w; }
    __syncthreads();

    if (threadIdx.x == 0) {
        float L = (s_l[0] + s_l[1]) + (s_l[2] + s_l[3]);
        int   V = (s_v[0] + s_v[1]) + (s_v[2] + s_v[3]);
        atomicAdd(&g_sum, (double)L);
        atomicAdd(&g_cnt, (unsigned long long)V);
        __threadfence();
        unsigned int n = atomicAdd(&g_arrive, 1u);
        if (n == (unsigned int)(NBLK_ - 1)) {
            __threadfence();
            double s = *((volatile double*)&g_sum);
            unsigned long long c = *((volatile unsigned long long*)&g_cnt);
            out[0] = (float)(s / (double)c);
            g_sum    = 0.0;
            g_cnt    = 0ull;
            g_arrive = 0u;
        }
    }
}

extern "C" void kernel_launch(void* const* d_in, const int* in_sizes, int n_in,
                              void* d_out, int out_size) {
    const float* pred = (const float*)d_in[0];
    const int*   tgt  = (const int*)d_in[1];
    float*       out  = (float*)d_out;

    bml_main<<<NBLK_, TPB_>>>(pred, tgt, out);
}